// round 8
// baseline (speedup 1.0000x reference)
#include <cuda_runtime.h>
#include <cuda_bf16.h>
#include <cstdint>

#define NB    500000
#define OBS   128
#define HD    64
#define AD    16
#define TPB   256
#define GRID  148
#define NBLK32 (NB / 32)          // 15625 32-row blocks, exact

// ---- SMEM layout (bytes) ----
#define OFF_B1    0               // 64 f32
#define OFF_BIH   256             // 192 f32
#define OFF_BHH   1024            // 192 f32
#define OFF_B2    1792            // 16 f32
#define RS1       272             // w1 row stride bytes (128 bf16 + 8 pad)
#define RSG       144             // 64-K matrices row stride bytes (64 bf16 + 8 pad)
#define OFF_W1HI  1856
#define OFF_W1LO  (OFF_W1HI + 64*RS1)
#define OFF_IHHI  (OFF_W1LO + 64*RS1)
#define OFF_IHLO  (OFF_IHHI + 192*RSG)
#define OFF_HHHI  (OFF_IHLO + 192*RSG)
#define OFF_HHLO  (OFF_HHHI + 192*RSG)
#define OFF_F2HI  (OFF_HHLO + 192*RSG)
#define OFF_F2LO  (OFF_F2HI + 16*RSG)
#define SMEM_BYTES (OFF_F2LO + 16*RSG)      // 151872

__device__ float g_nh_scratch[(size_t)NB * HD];

__device__ __forceinline__ float fast_sigmoid(float v) { return __fdividef(1.0f, 1.0f + __expf(-v)); }
__device__ __forceinline__ float fast_tanh(float v)    { return 1.0f - __fdividef(2.0f, __expf(2.0f * v) + 1.0f); }

__device__ __forceinline__ uint32_t smem_u32(const void* p) {
    uint32_t a;
    asm("{ .reg .u64 t; cvta.to.shared.u64 t, %1; cvt.u32.u64 %0, t; }" : "=r"(a) : "l"(p));
    return a;
}

__device__ __forceinline__ uint32_t packsplit(float x, float y, uint32_t& lo) {
    __nv_bfloat162 h = __floats2bfloat162_rn(x, y);
    float rx = x - __bfloat162float(h.x);
    float ry = y - __bfloat162float(h.y);
    __nv_bfloat162 l = __floats2bfloat162_rn(rx, ry);
    lo = *reinterpret_cast<uint32_t*>(&l);
    return *reinterpret_cast<uint32_t*>(&h);
}

__device__ __forceinline__ void mma16816(float d[4], const uint32_t a[4], uint32_t b0, uint32_t b1) {
    asm volatile("mma.sync.aligned.m16n8k16.row.col.f32.bf16.bf16.f32 "
                 "{%0,%1,%2,%3}, {%4,%5,%6,%7}, {%8,%9}, {%0,%1,%2,%3};"
                 : "+f"(d[0]), "+f"(d[1]), "+f"(d[2]), "+f"(d[3])
                 : "r"(a[0]), "r"(a[1]), "r"(a[2]), "r"(a[3]), "r"(b0), "r"(b1));
}

__device__ __forceinline__ void ldB4(uint32_t addr, uint32_t b[4]) {
    asm volatile("ldmatrix.sync.aligned.m8n8.x4.shared.b16 {%0,%1,%2,%3}, [%4];"
                 : "=r"(b[0]), "=r"(b[1]), "=r"(b[2]), "=r"(b[3]) : "r"(addr));
}

// K=32 block, 3-way hi/lo split (drops only lo*lo): 6 HMMA
__device__ __forceinline__ void mma_k32(float d[4],
        const uint32_t AhA[4], const uint32_t AhB[4],
        const uint32_t AlA[4], const uint32_t AlB[4],
        const uint32_t Bh[4],  const uint32_t Bl[4]) {
    mma16816(d, AhA, Bh[0], Bh[1]);
    mma16816(d, AhB, Bh[2], Bh[3]);
    mma16816(d, AlA, Bh[0], Bh[1]);
    mma16816(d, AlB, Bh[2], Bh[3]);
    mma16816(d, AhA, Bl[0], Bl[1]);
    mma16816(d, AhB, Bl[2], Bl[3]);
}

// 16x16 A-fragment (hi/lo) straight from global f32
__device__ __forceinline__ void ldA_g(const float* __restrict__ g, int S, int r, int c,
                                      uint32_t hi[4], uint32_t lo[4]) {
    float2 v;
    v = *(const float2*)(g + (size_t)r       * S + c);     hi[0] = packsplit(v.x, v.y, lo[0]);
    v = *(const float2*)(g + (size_t)(r + 8) * S + c);     hi[1] = packsplit(v.x, v.y, lo[1]);
    v = *(const float2*)(g + (size_t)r       * S + c + 8); hi[2] = packsplit(v.x, v.y, lo[2]);
    v = *(const float2*)(g + (size_t)(r + 8) * S + c + 8); hi[3] = packsplit(v.x, v.y, lo[3]);
}

__global__ void __launch_bounds__(TPB, 1)
gru_hmma_kernel(const float* __restrict__ x,   const float* __restrict__ h_in,
                const int*   __restrict__ mask,
                const float* __restrict__ fc1_w, const float* __restrict__ fc1_b,
                const float* __restrict__ w_ih,  const float* __restrict__ w_hh,
                const float* __restrict__ b_ih,  const float* __restrict__ b_hh,
                const float* __restrict__ fc2_w, const float* __restrict__ fc2_b,
                float* __restrict__ out_logits,  float* __restrict__ out_h)
{
    extern __shared__ char smem[];
    const int tid  = threadIdx.x;
    const int lane = tid & 31;
    const int wid  = tid >> 5;

    float* s_b1  = (float*)(smem + OFF_B1);
    float* s_bih = (float*)(smem + OFF_BIH);
    float* s_bhh = (float*)(smem + OFF_BHH);
    float* s_b2  = (float*)(smem + OFF_B2);

    if (out_h == nullptr) out_h = g_nh_scratch;

    // ---- stage weights once: f32 -> bf16 hi/lo, padded rows ----
    {
        for (int i = tid; i < 64 * 128; i += TPB) {
            int r = i >> 7, k = i & 127;
            float f = fc1_w[i];
            __nv_bfloat16 hv = __float2bfloat16_rn(f);
            *(__nv_bfloat16*)(smem + OFF_W1HI + r * RS1 + 2 * k) = hv;
            *(__nv_bfloat16*)(smem + OFF_W1LO + r * RS1 + 2 * k) =
                __float2bfloat16_rn(f - __bfloat162float(hv));
        }
        for (int i = tid; i < 192 * 64; i += TPB) {
            int r = i >> 6, k = i & 63;
            float f = w_ih[i];
            __nv_bfloat16 hv = __float2bfloat16_rn(f);
            *(__nv_bfloat16*)(smem + OFF_IHHI + r * RSG + 2 * k) = hv;
            *(__nv_bfloat16*)(smem + OFF_IHLO + r * RSG + 2 * k) =
                __float2bfloat16_rn(f - __bfloat162float(hv));
            f = w_hh[i];
            hv = __float2bfloat16_rn(f);
            *(__nv_bfloat16*)(smem + OFF_HHHI + r * RSG + 2 * k) = hv;
            *(__nv_bfloat16*)(smem + OFF_HHLO + r * RSG + 2 * k) =
                __float2bfloat16_rn(f - __bfloat162float(hv));
        }
        for (int i = tid; i < 16 * 64; i += TPB) {
            int r = i >> 6, k = i & 63;
            float f = fc2_w[i];
            __nv_bfloat16 hv = __float2bfloat16_rn(f);
            *(__nv_bfloat16*)(smem + OFF_F2HI + r * RSG + 2 * k) = hv;
            *(__nv_bfloat16*)(smem + OFF_F2LO + r * RSG + 2 * k) =
                __float2bfloat16_rn(f - __bfloat162float(hv));
        }
        for (int i = tid; i < 64;  i += TPB) s_b1[i] = fc1_b[i];
        for (int i = tid; i < 192; i += TPB) { s_bih[i] = b_ih[i]; s_bhh[i] = b_hh[i]; }
        for (int i = tid; i < 16;  i += TPB) s_b2[i] = fc2_b[i];
    }
    __syncthreads();

    const uint32_t sbase = smem_u32(smem);
    const uint32_t lA1 = (lane & 7) * RS1 + (lane >> 3) * 16;
    const uint32_t lAG = (lane & 7) * RSG + (lane >> 3) * 16;
    const uint32_t bW1h = sbase + OFF_W1HI + lA1, bW1l = sbase + OFF_W1LO + lA1;
    const uint32_t bIHh = sbase + OFF_IHHI + lAG, bIHl = sbase + OFF_IHLO + lAG;
    const uint32_t bHHh = sbase + OFF_HHHI + lAG, bHHl = sbase + OFF_HHLO + lAG;
    const uint32_t bF2h = sbase + OFF_F2HI + lAG, bF2l = sbase + OFF_F2LO + lAG;

    const int cb = 2 * (lane & 3);
    const int gwid  = blockIdx.x * 8 + wid;
    const int nwork = GRID * 8;

    for (int blk = gwid; blk < NBLK32; blk += nwork) {
        const int m0  = blk * 32;
        const int gr0 = m0 + (lane >> 2);       // half 0 base row
        const int gr1 = gr0 + 16;               // half 1 base row

        // ================= fc1: D = x @ w1^T (M32, N64, K128) =================
        float D0[8][4], D1[8][4];
        #pragma unroll
        for (int n = 0; n < 8; n++)
            #pragma unroll
            for (int i = 0; i < 4; i++) { D0[n][i] = 0.f; D1[n][i] = 0.f; }

        #pragma unroll
        for (int kk = 0; kk < 4; kk++) {
            uint32_t A0hA[4], A0lA[4], A0hB[4], A0lB[4];
            uint32_t A1hA[4], A1lA[4], A1hB[4], A1lB[4];
            ldA_g(x, OBS, gr0, kk * 32 + cb,      A0hA, A0lA);
            ldA_g(x, OBS, gr0, kk * 32 + 16 + cb, A0hB, A0lB);
            ldA_g(x, OBS, gr1, kk * 32 + cb,      A1hA, A1lA);
            ldA_g(x, OBS, gr1, kk * 32 + 16 + cb, A1hB, A1lB);
            #pragma unroll
            for (int n = 0; n < 8; n++) {
                uint32_t Bh[4], Bl[4];
                ldB4(bW1h + n * (8 * RS1) + kk * 64, Bh);
                ldB4(bW1l + n * (8 * RS1) + kk * 64, Bl);
                mma_k32(D0[n], A0hA, A0hB, A0lA, A0lB, Bh, Bl);
                mma_k32(D1[n], A1hA, A1hB, A1lA, A1lB, Bh, Bl);
            }
        }

        // a = tanh(D + b1) -> gate A-fragments (hi/lo), per half
        uint32_t Aah[2][4][4], Aal[2][4][4];
        #pragma unroll
        for (int n = 0; n < 8; n++)
            #pragma unroll
            for (int i = 0; i < 4; i++) {
                const float b = s_b1[8 * n + cb + (i & 1)];
                D0[n][i] = fast_tanh(D0[n][i] + b);
                D1[n][i] = fast_tanh(D1[n][i] + b);
            }
        #pragma unroll
        for (int c = 0; c < 4; c++) {
            Aah[0][c][0] = packsplit(D0[2*c][0],   D0[2*c][1],   Aal[0][c][0]);
            Aah[0][c][1] = packsplit(D0[2*c][2],   D0[2*c][3],   Aal[0][c][1]);
            Aah[0][c][2] = packsplit(D0[2*c+1][0], D0[2*c+1][1], Aal[0][c][2]);
            Aah[0][c][3] = packsplit(D0[2*c+1][2], D0[2*c+1][3], Aal[0][c][3]);
            Aah[1][c][0] = packsplit(D1[2*c][0],   D1[2*c][1],   Aal[1][c][0]);
            Aah[1][c][1] = packsplit(D1[2*c][2],   D1[2*c][3],   Aal[1][c][1]);
            Aah[1][c][2] = packsplit(D1[2*c+1][0], D1[2*c+1][1], Aal[1][c][2]);
            Aah[1][c][3] = packsplit(D1[2*c+1][2], D1[2*c+1][3], Aal[1][c][3]);
        }

        // h A-fragments straight from global
        uint32_t Ahh[2][4][4], Ahl[2][4][4];
        #pragma unroll
        for (int c = 0; c < 4; c++) {
            ldA_g(h_in, HD, gr0, c * 16 + cb, Ahh[0][c], Ahl[0][c]);
            ldA_g(h_in, HD, gr1, c * 16 + cb, Ahh[1][c], Ahl[1][c]);
        }

        const int mk[2][2] = { { mask[gr0], mask[gr0 + 8] },
                               { mask[gr1], mask[gr1 + 8] } };

        float rv[2][8][4];

        // ---- gate r (weight rows 0..63): per-n-tile accumulate + epilogue ----
        #pragma unroll
        for (int n = 0; n < 8; n++) {
            float Di[2][4], Dh[2][4];
            #pragma unroll
            for (int i = 0; i < 4; i++) { Di[0][i]=0.f; Di[1][i]=0.f; Dh[0][i]=0.f; Dh[1][i]=0.f; }
            #pragma unroll
            for (int kk = 0; kk < 2; kk++) {
                uint32_t Bh[4], Bl[4];
                ldB4(bIHh + n * (8 * RSG) + kk * 64, Bh);
                ldB4(bIHl + n * (8 * RSG) + kk * 64, Bl);
                mma_k32(Di[0], Aah[0][2*kk], Aah[0][2*kk+1], Aal[0][2*kk], Aal[0][2*kk+1], Bh, Bl);
                mma_k32(Di[1], Aah[1][2*kk], Aah[1][2*kk+1], Aal[1][2*kk], Aal[1][2*kk+1], Bh, Bl);
                ldB4(bHHh + n * (8 * RSG) + kk * 64, Bh);
                ldB4(bHHl + n * (8 * RSG) + kk * 64, Bl);
                mma_k32(Dh[0], Ahh[0][2*kk], Ahh[0][2*kk+1], Ahl[0][2*kk], Ahl[0][2*kk+1], Bh, Bl);
                mma_k32(Dh[1], Ahh[1][2*kk], Ahh[1][2*kk+1], Ahl[1][2*kk], Ahl[1][2*kk+1], Bh, Bl);
            }
            #pragma unroll
            for (int ht = 0; ht < 2; ht++)
                #pragma unroll
                for (int i = 0; i < 4; i++) {
                    const int col = 8 * n + cb + (i & 1);
                    rv[ht][n][i] = fast_sigmoid(Di[ht][i] + Dh[ht][i] + s_bih[col] + s_bhh[col]);
                }
        }

        // ---- gate n (weight rows 128..191): nv = tanh(i_n + b + r*(h_n + b)) ----
        #pragma unroll
        for (int n = 0; n < 8; n++) {
            float Di[2][4], Dh[2][4];
            #pragma unroll
            for (int i = 0; i < 4; i++) { Di[0][i]=0.f; Di[1][i]=0.f; Dh[0][i]=0.f; Dh[1][i]=0.f; }
            #pragma unroll
            for (int kk = 0; kk < 2; kk++) {
                uint32_t Bh[4], Bl[4];
                ldB4(bIHh + (128 + 8 * n) * RSG + kk * 64, Bh);
                ldB4(bIHl + (128 + 8 * n) * RSG + kk * 64, Bl);
                mma_k32(Di[0], Aah[0][2*kk], Aah[0][2*kk+1], Aal[0][2*kk], Aal[0][2*kk+1], Bh, Bl);
                mma_k32(Di[1], Aah[1][2*kk], Aah[1][2*kk+1], Aal[1][2*kk], Aal[1][2*kk+1], Bh, Bl);
                ldB4(bHHh + (128 + 8 * n) * RSG + kk * 64, Bh);
                ldB4(bHHl + (128 + 8 * n) * RSG + kk * 64, Bl);
                mma_k32(Dh[0], Ahh[0][2*kk], Ahh[0][2*kk+1], Ahl[0][2*kk], Ahl[0][2*kk+1], Bh, Bl);
                mma_k32(Dh[1], Ahh[1][2*kk], Ahh[1][2*kk+1], Ahl[1][2*kk], Ahl[1][2*kk+1], Bh, Bl);
            }
            #pragma unroll
            for (int ht = 0; ht < 2; ht++)
                #pragma unroll
                for (int i = 0; i < 4; i++) {
                    const int col = 8 * n + cb + (i & 1);
                    rv[ht][n][i] = fast_tanh(Di[ht][i] + s_bih[128 + col] +
                                             rv[ht][n][i] * (Dh[ht][i] + s_bhh[128 + col]));
                }
        }

        // ---- gate z (weight rows 64..127) + update + mask + store nh ----
        #pragma unroll
        for (int n = 0; n < 8; n++) {
            float Di[2][4], Dh[2][4];
            #pragma unroll
            for (int i = 0; i < 4; i++) { Di[0][i]=0.f; Di[1][i]=0.f; Dh[0][i]=0.f; Dh[1][i]=0.f; }
            #pragma unroll
            for (int kk = 0; kk < 2; kk++) {
                uint32_t Bh[4], Bl[4];
                ldB4(bIHh + (64 + 8 * n) * RSG + kk * 64, Bh);
                ldB4(bIHl + (64 + 8 * n) * RSG + kk * 64, Bl);
                mma_k32(Di[0], Aah[0][2*kk], Aah[0][2*kk+1], Aal[0][2*kk], Aal[0][2*kk+1], Bh, Bl);
                mma_k32(Di[1], Aah[1][2*kk], Aah[1][2*kk+1], Aal[1][2*kk], Aal[1][2*kk+1], Bh, Bl);
                ldB4(bHHh + (64 + 8 * n) * RSG + kk * 64, Bh);
                ldB4(bHHl + (64 + 8 * n) * RSG + kk * 64, Bl);
                mma_k32(Dh[0], Ahh[0][2*kk], Ahh[0][2*kk+1], Ahl[0][2*kk], Ahl[0][2*kk+1], Bh, Bl);
                mma_k32(Dh[1], Ahh[1][2*kk], Ahh[1][2*kk+1], Ahl[1][2*kk], Ahl[1][2*kk+1], Bh, Bl);
            }
            #pragma unroll
            for (int ht = 0; ht < 2; ht++) {
                const int grh = ht ? gr1 : gr0;
                #pragma unroll
                for (int i = 0; i < 4; i++) {
                    const int col = 8 * n + cb + (i & 1);
                    const float zv = fast_sigmoid(Di[ht][i] + Dh[ht][i] +
                                                  s_bih[64 + col] + s_bhh[64 + col]);
                    // recompose h_old from the hi/lo A-fragments
                    const int c = n >> 1, ri = ((n & 1) << 1) + (i >> 1);
                    __nv_bfloat162 hh = *reinterpret_cast<__nv_bfloat162*>(&Ahh[ht][c][ri]);
                    __nv_bfloat162 hl = *reinterpret_cast<__nv_bfloat162*>(&Ahl[ht][c][ri]);
                    const float hold = (i & 1) ? (__bfloat162float(hh.y) + __bfloat162float(hl.y))
                                               : (__bfloat162float(hh.x) + __bfloat162float(hl.x));
                    const float nvl  = rv[ht][n][i];
                    const float hu   = fmaf(zv, hold - nvl, nvl);
                    rv[ht][n][i] = ((i < 2) ? mk[ht][0] : mk[ht][1]) ? hu : hold;
                }
                *(float2*)(out_h + (size_t)grh       * HD + 8 * n + cb) =
                    make_float2(rv[ht][n][0], rv[ht][n][1]);
                *(float2*)(out_h + (size_t)(grh + 8) * HD + 8 * n + cb) =
                    make_float2(rv[ht][n][2], rv[ht][n][3]);
            }
        }

        // ================= fc2: logits = nh @ fc2^T (N16, K64) =================
        #pragma unroll
        for (int ht = 0; ht < 2; ht++)
            #pragma unroll
            for (int c = 0; c < 4; c++) {
                Aah[ht][c][0] = packsplit(rv[ht][2*c][0],   rv[ht][2*c][1],   Aal[ht][c][0]);
                Aah[ht][c][1] = packsplit(rv[ht][2*c][2],   rv[ht][2*c][3],   Aal[ht][c][1]);
                Aah[ht][c][2] = packsplit(rv[ht][2*c+1][0], rv[ht][2*c+1][1], Aal[ht][c][2]);
                Aah[ht][c][3] = packsplit(rv[ht][2*c+1][2], rv[ht][2*c+1][3], Aal[ht][c][3]);
            }
        #pragma unroll
        for (int nt = 0; nt < 2; nt++) {
            float Dl[2][4];
            #pragma unroll
            for (int i = 0; i < 4; i++) { Dl[0][i] = 0.f; Dl[1][i] = 0.f; }
            #pragma unroll
            for (int kk = 0; kk < 2; kk++) {
                uint32_t Bh[4], Bl[4];
                ldB4(bF2h + nt * (8 * RSG) + kk * 64, Bh);
                ldB4(bF2l + nt * (8 * RSG) + kk * 64, Bl);
                mma_k32(Dl[0], Aah[0][2*kk], Aah[0][2*kk+1], Aal[0][2*kk], Aal[0][2*kk+1], Bh, Bl);
                mma_k32(Dl[1], Aah[1][2*kk], Aah[1][2*kk+1], Aal[1][2*kk], Aal[1][2*kk+1], Bh, Bl);
            }
            const int col0 = 8 * nt + cb;
            #pragma unroll
            for (int ht = 0; ht < 2; ht++) {
                const int grh = ht ? gr1 : gr0;
                *(float2*)(out_logits + (size_t)grh       * AD + col0) =
                    make_float2(Dl[ht][0] + s_b2[col0], Dl[ht][1] + s_b2[col0 + 1]);
                *(float2*)(out_logits + (size_t)(grh + 8) * AD + col0) =
                    make_float2(Dl[ht][2] + s_b2[col0], Dl[ht][3] + s_b2[col0 + 1]);
            }
        }
    }
}

extern "C" void kernel_launch(void* const* d_in, const int* in_sizes, int n_in,
                              void* d_out, int out_size)
{
    const float* x    = (const float*)d_in[0];
    const float* hs   = (const float*)d_in[1];
    const int*   am   = (const int*)d_in[2];
    const float* fc1w = (const float*)d_in[3];
    const float* fc1b = (const float*)d_in[4];
    const float* wih  = (const float*)d_in[5];
    const float* whh  = (const float*)d_in[6];
    const float* bih  = (const float*)d_in[7];
    const float* bhh  = (const float*)d_in[8];
    const float* fc2w = (const float*)d_in[9];
    const float* fc2b = (const float*)d_in[10];

    float* out_logits = (float*)d_out;
    float* out_h = nullptr;
    if ((long long)out_size >= (long long)NB * (AD + HD))
        out_h = out_logits + (size_t)NB * AD;

    cudaFuncSetAttribute(gru_hmma_kernel,
                         cudaFuncAttributeMaxDynamicSharedMemorySize, SMEM_BYTES);

    gru_hmma_kernel<<<GRID, TPB, SMEM_BYTES>>>(
        x, hs, am, fc1w, fc1b, wih, whh, bih, bhh, fc2w, fc2b,
        out_logits, out_h);
}

// round 9
// speedup vs baseline: 1.2721x; 1.2721x over previous
#include <cuda_runtime.h>
#include <cuda_bf16.h>
#include <cstdint>

#define NB    500000
#define OBS   128
#define HD    64
#define AD    16
#define TPB   384
#define NWARP (TPB / 32)
#define GRID  148
#define NBLK  (NB / 16)          // 31250 16-row blocks, exact

// ---- SMEM layout (bytes) ----
#define OFF_B1    0               // 64 f32
#define OFF_BIH   256             // 192 f32
#define OFF_BHH   1024            // 192 f32
#define OFF_B2    1792            // 16 f32
#define RS1       272             // w1 row stride bytes (128 bf16 + 8 pad)
#define RSG       144             // 64-K matrices row stride bytes (64 bf16 + 8 pad)
#define OFF_W1HI  1856
#define OFF_W1LO  (OFF_W1HI + 64*RS1)
#define OFF_IHHI  (OFF_W1LO + 64*RS1)
#define OFF_IHLO  (OFF_IHHI + 192*RSG)
#define OFF_HHHI  (OFF_IHLO + 192*RSG)
#define OFF_HHLO  (OFF_HHHI + 192*RSG)
#define OFF_F2HI  (OFF_HHLO + 192*RSG)
#define OFF_F2LO  (OFF_F2HI + 16*RSG)
#define SMEM_BYTES (OFF_F2LO + 16*RSG)      // 151872

__device__ float g_nh_scratch[(size_t)NB * HD];

__device__ __forceinline__ float fast_sigmoid(float v) { return __fdividef(1.0f, 1.0f + __expf(-v)); }
__device__ __forceinline__ float fast_tanh(float v)    { return 1.0f - __fdividef(2.0f, __expf(2.0f * v) + 1.0f); }

__device__ __forceinline__ uint32_t smem_u32(const void* p) {
    uint32_t a;
    asm("{ .reg .u64 t; cvta.to.shared.u64 t, %1; cvt.u32.u64 %0, t; }" : "=r"(a) : "l"(p));
    return a;
}

__device__ __forceinline__ uint32_t packsplit(float x, float y, uint32_t& lo) {
    __nv_bfloat162 h = __floats2bfloat162_rn(x, y);
    float rx = x - __bfloat162float(h.x);
    float ry = y - __bfloat162float(h.y);
    __nv_bfloat162 l = __floats2bfloat162_rn(rx, ry);
    lo = *reinterpret_cast<uint32_t*>(&l);
    return *reinterpret_cast<uint32_t*>(&h);
}

__device__ __forceinline__ void mma16816(float d[4], const uint32_t a[4], uint32_t b0, uint32_t b1) {
    asm volatile("mma.sync.aligned.m16n8k16.row.col.f32.bf16.bf16.f32 "
                 "{%0,%1,%2,%3}, {%4,%5,%6,%7}, {%8,%9}, {%0,%1,%2,%3};"
                 : "+f"(d[0]), "+f"(d[1]), "+f"(d[2]), "+f"(d[3])
                 : "r"(a[0]), "r"(a[1]), "r"(a[2]), "r"(a[3]), "r"(b0), "r"(b1));
}

__device__ __forceinline__ void ldB4(uint32_t addr, uint32_t b[4]) {
    asm volatile("ldmatrix.sync.aligned.m8n8.x4.shared.b16 {%0,%1,%2,%3}, [%4];"
                 : "=r"(b[0]), "=r"(b[1]), "=r"(b[2]), "=r"(b[3]) : "r"(addr));
}

// K=32 block, 3-way hi/lo split (drops only lo*lo): 6 HMMA
__device__ __forceinline__ void mma_k32(float d[4],
        const uint32_t AhA[4], const uint32_t AhB[4],
        const uint32_t AlA[4], const uint32_t AlB[4],
        const uint32_t Bh[4],  const uint32_t Bl[4]) {
    mma16816(d, AhA, Bh[0], Bh[1]);
    mma16816(d, AhB, Bh[2], Bh[3]);
    mma16816(d, AlA, Bh[0], Bh[1]);
    mma16816(d, AlB, Bh[2], Bh[3]);
    mma16816(d, AhA, Bl[0], Bl[1]);
    mma16816(d, AhB, Bl[2], Bl[3]);
}

// 16x16 A-fragment (hi/lo) straight from global f32
__device__ __forceinline__ void ldA_g(const float* __restrict__ g, int S, int r, int c,
                                      uint32_t hi[4], uint32_t lo[4]) {
    float2 v;
    v = *(const float2*)(g + (size_t)r       * S + c);     hi[0] = packsplit(v.x, v.y, lo[0]);
    v = *(const float2*)(g + (size_t)(r + 8) * S + c);     hi[1] = packsplit(v.x, v.y, lo[1]);
    v = *(const float2*)(g + (size_t)r       * S + c + 8); hi[2] = packsplit(v.x, v.y, lo[2]);
    v = *(const float2*)(g + (size_t)(r + 8) * S + c + 8); hi[3] = packsplit(v.x, v.y, lo[3]);
}

// one gate n-tile: Di += a@Wih_tile, Dh += h@Whh_tile  (K=64)
__device__ __forceinline__ void gate_tile(uint32_t aIHh, uint32_t aIHl,
                                          uint32_t aHHh, uint32_t aHHl,
                                          const uint32_t (&Aah)[4][4], const uint32_t (&Aal)[4][4],
                                          const uint32_t (&Ahh)[4][4], const uint32_t (&Ahl)[4][4],
                                          float Di[4], float Dh[4]) {
    #pragma unroll
    for (int kk = 0; kk < 2; kk++) {
        uint32_t Bh[4], Bl[4];
        ldB4(aIHh + kk * 64, Bh);
        ldB4(aIHl + kk * 64, Bl);
        mma_k32(Di, Aah[2*kk], Aah[2*kk+1], Aal[2*kk], Aal[2*kk+1], Bh, Bl);
        ldB4(aHHh + kk * 64, Bh);
        ldB4(aHHl + kk * 64, Bl);
        mma_k32(Dh, Ahh[2*kk], Ahh[2*kk+1], Ahl[2*kk], Ahl[2*kk+1], Bh, Bl);
    }
}

__global__ void __launch_bounds__(TPB, 1)
gru_hmma_kernel(const float* __restrict__ x,   const float* __restrict__ h_in,
                const int*   __restrict__ mask,
                const float* __restrict__ fc1_w, const float* __restrict__ fc1_b,
                const float* __restrict__ w_ih,  const float* __restrict__ w_hh,
                const float* __restrict__ b_ih,  const float* __restrict__ b_hh,
                const float* __restrict__ fc2_w, const float* __restrict__ fc2_b,
                float* __restrict__ out_logits,  float* __restrict__ out_h)
{
    extern __shared__ char smem[];
    const int tid  = threadIdx.x;
    const int lane = tid & 31;
    const int wid  = tid >> 5;

    float* s_b1  = (float*)(smem + OFF_B1);
    float* s_bih = (float*)(smem + OFF_BIH);
    float* s_bhh = (float*)(smem + OFF_BHH);
    float* s_b2  = (float*)(smem + OFF_B2);

    if (out_h == nullptr) out_h = g_nh_scratch;

    // ---- stage weights once: f32 -> bf16 hi/lo, padded rows ----
    {
        for (int i = tid; i < 64 * 128; i += TPB) {
            int r = i >> 7, k = i & 127;
            float f = fc1_w[i];
            __nv_bfloat16 hv = __float2bfloat16_rn(f);
            *(__nv_bfloat16*)(smem + OFF_W1HI + r * RS1 + 2 * k) = hv;
            *(__nv_bfloat16*)(smem + OFF_W1LO + r * RS1 + 2 * k) =
                __float2bfloat16_rn(f - __bfloat162float(hv));
        }
        for (int i = tid; i < 192 * 64; i += TPB) {
            int r = i >> 6, k = i & 63;
            float f = w_ih[i];
            __nv_bfloat16 hv = __float2bfloat16_rn(f);
            *(__nv_bfloat16*)(smem + OFF_IHHI + r * RSG + 2 * k) = hv;
            *(__nv_bfloat16*)(smem + OFF_IHLO + r * RSG + 2 * k) =
                __float2bfloat16_rn(f - __bfloat162float(hv));
            f = w_hh[i];
            hv = __float2bfloat16_rn(f);
            *(__nv_bfloat16*)(smem + OFF_HHHI + r * RSG + 2 * k) = hv;
            *(__nv_bfloat16*)(smem + OFF_HHLO + r * RSG + 2 * k) =
                __float2bfloat16_rn(f - __bfloat162float(hv));
        }
        for (int i = tid; i < 16 * 64; i += TPB) {
            int r = i >> 6, k = i & 63;
            float f = fc2_w[i];
            __nv_bfloat16 hv = __float2bfloat16_rn(f);
            *(__nv_bfloat16*)(smem + OFF_F2HI + r * RSG + 2 * k) = hv;
            *(__nv_bfloat16*)(smem + OFF_F2LO + r * RSG + 2 * k) =
                __float2bfloat16_rn(f - __bfloat162float(hv));
        }
        for (int i = tid; i < 64;  i += TPB) s_b1[i] = fc1_b[i];
        for (int i = tid; i < 192; i += TPB) { s_bih[i] = b_ih[i]; s_bhh[i] = b_hh[i]; }
        for (int i = tid; i < 16;  i += TPB) s_b2[i] = fc2_b[i];
    }
    __syncthreads();

    const uint32_t sbase = smem_u32(smem);
    const uint32_t lA1 = (lane & 7) * RS1 + (lane >> 3) * 16;
    const uint32_t lAG = (lane & 7) * RSG + (lane >> 3) * 16;
    const uint32_t bW1h = sbase + OFF_W1HI + lA1, bW1l = sbase + OFF_W1LO + lA1;
    const uint32_t bIHh = sbase + OFF_IHHI + lAG, bIHl = sbase + OFF_IHLO + lAG;
    const uint32_t bHHh = sbase + OFF_HHHI + lAG, bHHl = sbase + OFF_HHLO + lAG;
    const uint32_t bF2h = sbase + OFF_F2HI + lAG, bF2l = sbase + OFF_F2LO + lAG;

    const int cb = 2 * (lane & 3);
    const int gwid  = blockIdx.x * NWARP + wid;
    const int nwork = GRID * NWARP;

    for (int blk = gwid; blk < NBLK; blk += nwork) {
        const int m0 = blk * 16;
        const int gr = m0 + (lane >> 2);

        // ================= fc1: D = x @ w1^T (M16, N64, K128) =================
        float D[8][4];
        #pragma unroll
        for (int n = 0; n < 8; n++)
            #pragma unroll
            for (int i = 0; i < 4; i++) D[n][i] = 0.f;

        #pragma unroll
        for (int kk = 0; kk < 4; kk++) {
            uint32_t AhA[4], AlA[4], AhB[4], AlB[4];
            ldA_g(x, OBS, gr, kk * 32 + cb,      AhA, AlA);
            ldA_g(x, OBS, gr, kk * 32 + 16 + cb, AhB, AlB);
            #pragma unroll
            for (int n = 0; n < 8; n++) {
                uint32_t Bh[4], Bl[4];
                ldB4(bW1h + n * (8 * RS1) + kk * 64, Bh);
                ldB4(bW1l + n * (8 * RS1) + kk * 64, Bl);
                mma_k32(D[n], AhA, AhB, AlA, AlB, Bh, Bl);
            }
        }

        // a = tanh(D + b1) -> gate A-fragments (hi/lo)
        uint32_t Aah[4][4], Aal[4][4];
        #pragma unroll
        for (int n = 0; n < 8; n++)
            #pragma unroll
            for (int i = 0; i < 4; i++)
                D[n][i] = fast_tanh(D[n][i] + s_b1[8 * n + cb + (i & 1)]);
        #pragma unroll
        for (int c = 0; c < 4; c++) {
            Aah[c][0] = packsplit(D[2*c][0],   D[2*c][1],   Aal[c][0]);
            Aah[c][1] = packsplit(D[2*c][2],   D[2*c][3],   Aal[c][1]);
            Aah[c][2] = packsplit(D[2*c+1][0], D[2*c+1][1], Aal[c][2]);
            Aah[c][3] = packsplit(D[2*c+1][2], D[2*c+1][3], Aal[c][3]);
        }

        // h A-fragments straight from global
        uint32_t Ahh[4][4], Ahl[4][4];
        #pragma unroll
        for (int c = 0; c < 4; c++)
            ldA_g(h_in, HD, gr, c * 16 + cb, Ahh[c], Ahl[c]);

        const int mA = mask[gr];
        const int mB = mask[gr + 8];

        float rv[8][4];   // r -> n -> nh, in place

        // ---- gate r (weight rows 0..63), per-n-tile epilogue ----
        #pragma unroll
        for (int n = 0; n < 8; n++) {
            float Di[4] = {0.f, 0.f, 0.f, 0.f}, Dh[4] = {0.f, 0.f, 0.f, 0.f};
            gate_tile(bIHh + 8*n*RSG, bIHl + 8*n*RSG, bHHh + 8*n*RSG, bHHl + 8*n*RSG,
                      Aah, Aal, Ahh, Ahl, Di, Dh);
            #pragma unroll
            for (int i = 0; i < 4; i++) {
                const int col = 8 * n + cb + (i & 1);
                rv[n][i] = fast_sigmoid(Di[i] + Dh[i] + s_bih[col] + s_bhh[col]);
            }
        }

        // ---- gate n (weight rows 128..191): nv = tanh(i_n + b + r*(h_n + b)) ----
        #pragma unroll
        for (int n = 0; n < 8; n++) {
            float Di[4] = {0.f, 0.f, 0.f, 0.f}, Dh[4] = {0.f, 0.f, 0.f, 0.f};
            gate_tile(bIHh + (128+8*n)*RSG, bIHl + (128+8*n)*RSG,
                      bHHh + (128+8*n)*RSG, bHHl + (128+8*n)*RSG,
                      Aah, Aal, Ahh, Ahl, Di, Dh);
            #pragma unroll
            for (int i = 0; i < 4; i++) {
                const int col = 8 * n + cb + (i & 1);
                rv[n][i] = fast_tanh(Di[i] + s_bih[128 + col] +
                                     rv[n][i] * (Dh[i] + s_bhh[128 + col]));
            }
        }

        // ---- gate z (weight rows 64..127) + update + mask + store nh ----
        #pragma unroll
        for (int n = 0; n < 8; n++) {
            float Di[4] = {0.f, 0.f, 0.f, 0.f}, Dh[4] = {0.f, 0.f, 0.f, 0.f};
            gate_tile(bIHh + (64+8*n)*RSG, bIHl + (64+8*n)*RSG,
                      bHHh + (64+8*n)*RSG, bHHl + (64+8*n)*RSG,
                      Aah, Aal, Ahh, Ahl, Di, Dh);
            #pragma unroll
            for (int i = 0; i < 4; i++) {
                const int col = 8 * n + cb + (i & 1);
                const float zv = fast_sigmoid(Di[i] + Dh[i] + s_bih[64 + col] + s_bhh[64 + col]);
                const int c = n >> 1, ri = ((n & 1) << 1) + (i >> 1);
                __nv_bfloat162 hh = *reinterpret_cast<__nv_bfloat162*>(&Ahh[c][ri]);
                __nv_bfloat162 hl = *reinterpret_cast<__nv_bfloat162*>(&Ahl[c][ri]);
                const float hold = (i & 1) ? (__bfloat162float(hh.y) + __bfloat162float(hl.y))
                                           : (__bfloat162float(hh.x) + __bfloat162float(hl.x));
                const float nvl  = rv[n][i];
                const float hu   = fmaf(zv, hold - nvl, nvl);
                rv[n][i] = ((i < 2) ? mA : mB) ? hu : hold;
            }
            *(float2*)(out_h + (size_t)gr       * HD + 8 * n + cb) = make_float2(rv[n][0], rv[n][1]);
            *(float2*)(out_h + (size_t)(gr + 8) * HD + 8 * n + cb) = make_float2(rv[n][2], rv[n][3]);
        }

        // ================= fc2: logits = nh @ fc2^T (N16, K64) =================
        #pragma unroll
        for (int c = 0; c < 4; c++) {
            Aah[c][0] = packsplit(rv[2*c][0],   rv[2*c][1],   Aal[c][0]);
            Aah[c][1] = packsplit(rv[2*c][2],   rv[2*c][3],   Aal[c][1]);
            Aah[c][2] = packsplit(rv[2*c+1][0], rv[2*c+1][1], Aal[c][2]);
            Aah[c][3] = packsplit(rv[2*c+1][2], rv[2*c+1][3], Aal[c][3]);
        }
        #pragma unroll
        for (int nt = 0; nt < 2; nt++) {
            float Dl[4] = {0.f, 0.f, 0.f, 0.f};
            #pragma unroll
            for (int kk = 0; kk < 2; kk++) {
                uint32_t Bh[4], Bl[4];
                ldB4(bF2h + nt * (8 * RSG) + kk * 64, Bh);
                ldB4(bF2l + nt * (8 * RSG) + kk * 64, Bl);
                mma_k32(Dl, Aah[2*kk], Aah[2*kk+1], Aal[2*kk], Aal[2*kk+1], Bh, Bl);
            }
            const int col0 = 8 * nt + cb;
            *(float2*)(out_logits + (size_t)gr       * AD + col0) =
                make_float2(Dl[0] + s_b2[col0], Dl[1] + s_b2[col0 + 1]);
            *(float2*)(out_logits + (size_t)(gr + 8) * AD + col0) =
                make_float2(Dl[2] + s_b2[col0], Dl[3] + s_b2[col0 + 1]);
        }
    }
}

extern "C" void kernel_launch(void* const* d_in, const int* in_sizes, int n_in,
                              void* d_out, int out_size)
{
    const float* x    = (const float*)d_in[0];
    const float* hs   = (const float*)d_in[1];
    const int*   am   = (const int*)d_in[2];
    const float* fc1w = (const float*)d_in[3];
    const float* fc1b = (const float*)d_in[4];
    const float* wih  = (const float*)d_in[5];
    const float* whh  = (const float*)d_in[6];
    const float* bih  = (const float*)d_in[7];
    const float* bhh  = (const float*)d_in[8];
    const float* fc2w = (const float*)d_in[9];
    const float* fc2b = (const float*)d_in[10];

    float* out_logits = (float*)d_out;
    float* out_h = nullptr;
    if ((long long)out_size >= (long long)NB * (AD + HD))
        out_h = out_logits + (size_t)NB * AD;

    cudaFuncSetAttribute(gru_hmma_kernel,
                         cudaFuncAttributeMaxDynamicSharedMemorySize, SMEM_BYTES);

    gru_hmma_kernel<<<GRID, TPB, SMEM_BYTES>>>(
        x, hs, am, fc1w, fc1b, wih, whh, bih, bhh, fc2w, fc2b,
        out_logits, out_h);
}